// round 5
// baseline (speedup 1.0000x reference)
#include <cuda_runtime.h>
#include <math.h>

#define N_NODES 100000
#define N_EDGES 3200000
#define K_IN    1433
#define C1      16

// ---------------- scratch (static device globals; no allocation) ------------
__device__ __align__(16) int   g_cnt[N_NODES];
__device__ __align__(16) int   g_off[N_NODES + 4];
__device__ __align__(16) int   g_pos[N_NODES];
__device__ __align__(16) float g_dinv[N_NODES];
__device__ __align__(16) int   g_ecol[N_EDGES];
__device__ __align__(16) float g_h1[N_NODES * 16];
__device__ __align__(16) float g_h2[N_NODES * 8];

// ---------------- degree / CSR build ---------------------------------------
__global__ void k_zero_cnt() {
    int i = blockIdx.x * blockDim.x + threadIdx.x;
    if (i * 4 < N_NODES) ((int4*)g_cnt)[i] = make_int4(0, 0, 0, 0);
}

__global__ void k_count(const int* __restrict__ row) {
    int i = blockIdx.x * blockDim.x + threadIdx.x;     // 8 edges per thread
    if (i * 8 >= N_EDGES) return;
    int4 r0 = ((const int4*)row)[2 * i];
    int4 r1 = ((const int4*)row)[2 * i + 1];
    atomicAdd(&g_cnt[r0.x], 1);
    atomicAdd(&g_cnt[r0.y], 1);
    atomicAdd(&g_cnt[r0.z], 1);
    atomicAdd(&g_cnt[r0.w], 1);
    atomicAdd(&g_cnt[r1.x], 1);
    atomicAdd(&g_cnt[r1.y], 1);
    atomicAdd(&g_cnt[r1.z], 1);
    atomicAdd(&g_cnt[r1.w], 1);
}

// single-block exclusive scan of counts -> offsets; also dinv = rsqrt(deg+1)
__global__ void k_scan() {
    const int T = 1024, ACT = 1000, CH4 = 25;          // 1000*100 = 100000
    int t = threadIdx.x;
    __shared__ int ps[T];
    int sum = 0;
    if (t < ACT) {
        const int4* c4 = (const int4*)g_cnt + t * CH4;
#pragma unroll
        for (int i = 0; i < CH4; i++) { int4 v = c4[i]; sum += v.x + v.y + v.z + v.w; }
    }
    ps[t] = sum;
    __syncthreads();
    for (int off = 1; off < T; off <<= 1) {
        int v = (t >= off) ? ps[t - off] : 0;
        __syncthreads();
        ps[t] += v;
        __syncthreads();
    }
    if (t < ACT) {
        int run = (t > 0) ? ps[t - 1] : 0;
        const int4* c4 = (const int4*)g_cnt + t * CH4;
        int4*   o4 = (int4*)g_off + t * CH4;
        int4*   p4 = (int4*)g_pos + t * CH4;
        float4* d4 = (float4*)g_dinv + t * CH4;
#pragma unroll 5
        for (int i = 0; i < CH4; i++) {
            int4 v = c4[i];
            int4 o;
            o.x = run; o.y = o.x + v.x; o.z = o.y + v.y; o.w = o.z + v.z;
            run = o.w + v.w;
            o4[i] = o; p4[i] = o;
            float4 dv;
            dv.x = rsqrtf((float)(v.x + 1)); dv.y = rsqrtf((float)(v.y + 1));
            dv.z = rsqrtf((float)(v.z + 1)); dv.w = rsqrtf((float)(v.w + 1));
            d4[i] = dv;
        }
        if (t == ACT - 1) g_off[N_NODES] = run;
    }
}

__global__ void k_place(const int* __restrict__ row, const int* __restrict__ col) {
    int i = blockIdx.x * blockDim.x + threadIdx.x;     // 8 edges per thread
    if (i * 8 >= N_EDGES) return;
    int4 r0 = ((const int4*)row)[2 * i];
    int4 r1 = ((const int4*)row)[2 * i + 1];
    int4 c0 = ((const int4*)col)[2 * i];
    int4 c1 = ((const int4*)col)[2 * i + 1];
    int p0 = atomicAdd(&g_pos[r0.x], 1);
    int p1 = atomicAdd(&g_pos[r0.y], 1);
    int p2 = atomicAdd(&g_pos[r0.z], 1);
    int p3 = atomicAdd(&g_pos[r0.w], 1);
    int p4 = atomicAdd(&g_pos[r1.x], 1);
    int p5 = atomicAdd(&g_pos[r1.y], 1);
    int p6 = atomicAdd(&g_pos[r1.z], 1);
    int p7 = atomicAdd(&g_pos[r1.w], 1);
    g_ecol[p0] = c0.x;
    g_ecol[p1] = c0.y;
    g_ecol[p2] = c0.z;
    g_ecol[p3] = c0.w;
    g_ecol[p4] = c1.x;
    g_ecol[p5] = c1.y;
    g_ecol[p6] = c1.z;
    g_ecol[p7] = c1.w;
}

// ---------------- GEMM1: h1 = x @ W1  (R3 proven version) --------------------
#define G1_BLOCK 256
#define G1_MT    680
#define G1_KT    8
#define G1_MTP   681
#define G1_R     3
#define G1_NT    ((K_IN + G1_KT - 1) / G1_KT)
#define G1_LD    ((G1_MT * G1_KT + G1_BLOCK - 1) / G1_BLOCK)
#define WS_PAD_K 1440
#define G1_SMEM_FLOATS (WS_PAD_K * C1 + 2 * G1_KT * G1_MTP + 128)
#define G1_SMEM_BYTES  (G1_SMEM_FLOATS * 4)

__device__ __forceinline__ void ffma2(unsigned long long& d,
                                      unsigned long long a,
                                      unsigned long long b) {
    asm("fma.rn.f32x2 %0, %1, %2, %0;" : "+l"(d) : "l"(a), "l"(b));
}

__global__ void __launch_bounds__(G1_BLOCK, 1)
k_gemm1(const float* __restrict__ x, const float* __restrict__ W1) {
    extern __shared__ float sm[];
    float* ws = sm;                       // [WS_PAD_K * 16]
    float* xs = sm + WS_PAD_K * C1;       // [2][G1_KT][G1_MTP]

    const int tid = threadIdx.x;
    const int m0  = blockIdx.x * G1_MT;

    {
        const float4* W4  = (const float4*)W1;
        float4*       ws4 = (float4*)ws;
        const int nW = K_IN * C1 / 4;
        const int nP = WS_PAD_K * C1 / 4;
        for (int i = tid; i < nP; i += G1_BLOCK) {
            float4 v = make_float4(0.f, 0.f, 0.f, 0.f);
            if (i < nW) v = W4[i];
            ws4[i] = v;
        }
    }

    unsigned long long acc2[G1_R][8];
#pragma unroll
    for (int r = 0; r < G1_R; r++)
#pragma unroll
        for (int c = 0; c < 8; c++) acc2[r][c] = 0ull;

    float st[G1_LD];

#pragma unroll
    for (int u = 0; u < G1_LD; u++) {
        int i = tid + u * G1_BLOCK;
        float v = 0.f;
        if (i < G1_MT * G1_KT) {
            int k = i & (G1_KT - 1);
            int m = i >> 3;
            int gm = m0 + m, gk = k;
            if (gm < N_NODES && gk < K_IN) v = x[(size_t)gm * K_IN + gk];
        }
        st[u] = v;
    }
#pragma unroll
    for (int u = 0; u < G1_LD; u++) {
        int i = tid + u * G1_BLOCK;
        if (i < G1_MT * G1_KT) {
            int k = i & (G1_KT - 1);
            int m = i >> 3;
            xs[k * G1_MTP + m] = st[u];
        }
    }
    __syncthreads();

    for (int t = 0; t < G1_NT; t++) {
        if (t + 1 < G1_NT) {
            int k0n = (t + 1) * G1_KT;
#pragma unroll
            for (int u = 0; u < G1_LD; u++) {
                int i = tid + u * G1_BLOCK;
                float v = 0.f;
                if (i < G1_MT * G1_KT) {
                    int k = i & (G1_KT - 1);
                    int m = i >> 3;
                    int gm = m0 + m, gk = k0n + k;
                    if (gm < N_NODES && gk < K_IN) v = x[(size_t)gm * K_IN + gk];
                }
                st[u] = v;
            }
        }

        const float* xb = xs + (t & 1) * (G1_KT * G1_MTP);
        const int k0 = t * G1_KT;
#pragma unroll
        for (int k = 0; k < G1_KT; k++) {
            const ulonglong2* wrow = (const ulonglong2*)(ws + (k0 + k) * C1);
            ulonglong2 wa = wrow[0], wb = wrow[1], wc = wrow[2], wd = wrow[3];
#pragma unroll
            for (int r = 0; r < G1_R; r++) {
                float xv = xb[k * G1_MTP + (r * G1_BLOCK + tid)];
                unsigned long long xv2;
                asm("mov.b64 %0, {%1, %1};" : "=l"(xv2) : "f"(xv));
                ffma2(acc2[r][0], xv2, wa.x);
                ffma2(acc2[r][1], xv2, wa.y);
                ffma2(acc2[r][2], xv2, wb.x);
                ffma2(acc2[r][3], xv2, wb.y);
                ffma2(acc2[r][4], xv2, wc.x);
                ffma2(acc2[r][5], xv2, wc.y);
                ffma2(acc2[r][6], xv2, wd.x);
                ffma2(acc2[r][7], xv2, wd.y);
            }
        }
        __syncthreads();

        if (t + 1 < G1_NT) {
            float* xbn = xs + ((t + 1) & 1) * (G1_KT * G1_MTP);
#pragma unroll
            for (int u = 0; u < G1_LD; u++) {
                int i = tid + u * G1_BLOCK;
                if (i < G1_MT * G1_KT) {
                    int k = i & (G1_KT - 1);
                    int m = i >> 3;
                    xbn[k * G1_MTP + m] = st[u];
                }
            }
        }
        __syncthreads();
    }

#pragma unroll
    for (int r = 0; r < G1_R; r++) {
        int lm = r * G1_BLOCK + tid;
        int m  = m0 + lm;
        if (lm < G1_MT && m < N_NODES) {
            float4* o = (float4*)(g_h1 + (size_t)m * 16);
#pragma unroll
            for (int p = 0; p < 4; p++) {
                float2 f0, f1;
                asm("mov.b64 {%0, %1}, %2;" : "=f"(f0.x), "=f"(f0.y) : "l"(acc2[r][2 * p]));
                asm("mov.b64 {%0, %1}, %2;" : "=f"(f1.x), "=f"(f1.y) : "l"(acc2[r][2 * p + 1]));
                o[p] = make_float4(f0.x, f0.y, f1.x, f1.y);
            }
        }
    }
}

// -------- aggregation 1 + bias + relu + GEMM2 fused: ONE WARP PER NODE -------
// lane = e*4 + q : 8 edge sublanes, 4 channel-quads
__global__ void __launch_bounds__(256)
k_agg1(const float* __restrict__ b1, const float* __restrict__ W2) {
    __shared__ float w2s[16 * 7];
    if (threadIdx.x < 16 * 7) w2s[threadIdx.x] = W2[threadIdx.x];
    __syncthreads();

    int g = (blockIdx.x * blockDim.x + threadIdx.x) >> 5;   // node == warp
    if (g >= N_NODES) return;
    int lane = threadIdx.x & 31;
    int e = lane >> 2, q = lane & 3;

    int s = g_off[g];
    int deg = g_off[g + 1] - s;
    const int* cols = g_ecol + s;

    float4 acc = make_float4(0.f, 0.f, 0.f, 0.f);
    for (int i = e; i < deg; i += 8) {
        int c = __ldg(cols + i);
        float dw = g_dinv[c];
        float4 hv = *(const float4*)(g_h1 + (size_t)c * 16 + q * 4);
        acc.x += hv.x * dw; acc.y += hv.y * dw;
        acc.z += hv.z * dw; acc.w += hv.w * dw;
    }

    // reduce over edge sublanes (e): xor 16, 8, 4
#pragma unroll
    for (int o = 16; o >= 4; o >>= 1) {
        acc.x += __shfl_xor_sync(0xffffffffu, acc.x, o);
        acc.y += __shfl_xor_sync(0xffffffffu, acc.y, o);
        acc.z += __shfl_xor_sync(0xffffffffu, acc.z, o);
        acc.w += __shfl_xor_sync(0xffffffffu, acc.w, o);
    }

    float di = g_dinv[g];
    float4 self = *(const float4*)(g_h1 + (size_t)g * 16 + q * 4);
    float4 bb   = ((const float4*)b1)[q];
    float v0 = fmaxf(bb.x + di * (acc.x + di * self.x), 0.f);
    float v1 = fmaxf(bb.y + di * (acc.y + di * self.y), 0.f);
    float v2 = fmaxf(bb.z + di * (acc.z + di * self.z), 0.f);
    float v3 = fmaxf(bb.w + di * (acc.w + di * self.w), 0.f);

    // fused GEMM2: lane's quad q holds input channels 4q..4q+3
    float h2a[7];
    const float* w2r = w2s + (4 * q) * 7;
#pragma unroll
    for (int c2 = 0; c2 < 7; c2++)
        h2a[c2] = v0 * w2r[c2] + v1 * w2r[7 + c2] + v2 * w2r[14 + c2] + v3 * w2r[21 + c2];
#pragma unroll
    for (int o = 1; o <= 2; o <<= 1)
#pragma unroll
        for (int c2 = 0; c2 < 7; c2++)
            h2a[c2] += __shfl_xor_sync(0xffffffffu, h2a[c2], o);

    if (lane == 0) {
        float4* o4 = (float4*)(g_h2 + (size_t)g * 8);
        o4[0] = make_float4(h2a[0], h2a[1], h2a[2], h2a[3]);
        o4[1] = make_float4(h2a[4], h2a[5], h2a[6], 0.f);
    }
}

// -------- aggregation 2 + bias + log_softmax: ONE WARP PER NODE --------------
// lane = e*4 + q : 8 edge sublanes, 4 channel-pairs (q=3 pair = {ch6, pad})
__global__ void __launch_bounds__(256)
k_agg2(const float* __restrict__ b2, float* __restrict__ out) {
    int g = (blockIdx.x * blockDim.x + threadIdx.x) >> 5;
    if (g >= N_NODES) return;
    int lane = threadIdx.x & 31;
    int e = lane >> 2, q = lane & 3;

    int s = g_off[g];
    int deg = g_off[g + 1] - s;
    const int* cols = g_ecol + s;

    float a0 = 0.f, a1 = 0.f;
    for (int i = e; i < deg; i += 8) {
        int c = __ldg(cols + i);
        float dw = g_dinv[c];
        float2 hv = *(const float2*)(g_h2 + (size_t)c * 8 + q * 2);
        a0 += hv.x * dw;
        a1 += hv.y * dw;
    }
#pragma unroll
    for (int o = 16; o >= 4; o >>= 1) {
        a0 += __shfl_xor_sync(0xffffffffu, a0, o);
        a1 += __shfl_xor_sync(0xffffffffu, a1, o);
    }

    float di = g_dinv[g];
    float dd = di * di;
    float2 self = *(const float2*)(g_h2 + (size_t)g * 8 + q * 2);
    float bb0 = b2[2 * q];
    float bb1 = (q < 3) ? b2[2 * q + 1] : 0.f;
    a0 = bb0 + di * a0 + dd * self.x;
    a1 = bb1 + di * a1 + dd * self.y;       // q==3: h2 pad col is 0; a1 = bb1

    // log_softmax over the 7 valid channels
    float m = (q == 3) ? a0 : fmaxf(a0, a1);
    m = fmaxf(m, __shfl_xor_sync(0xffffffffu, m, 1, 4));
    m = fmaxf(m, __shfl_xor_sync(0xffffffffu, m, 2, 4));
    float e0 = expf(a0 - m);
    float e1 = (q == 3) ? 0.f : expf(a1 - m);
    float ss = e0 + e1;
    ss += __shfl_xor_sync(0xffffffffu, ss, 1, 4);
    ss += __shfl_xor_sync(0xffffffffu, ss, 2, 4);
    float ls = m + logf(ss);

    if (e == 0) {   // lanes 0..3 store
        out[(size_t)g * 7 + 2 * q] = a0 - ls;
        if (q < 3) out[(size_t)g * 7 + 2 * q + 1] = a1 - ls;
    }
}

// ---------------- launch ------------------------------------------------------
extern "C" void kernel_launch(void* const* d_in, const int* in_sizes, int n_in,
                              void* d_out, int out_size) {
    const float* x   = (const float*)d_in[0];
    const int*   row = (const int*)  d_in[1];
    const int*   col = (const int*)  d_in[2];
    const float* W1  = (const float*)d_in[3];
    const float* b1  = (const float*)d_in[4];
    const float* W2  = (const float*)d_in[5];
    const float* b2  = (const float*)d_in[6];
    float* out = (float*)d_out;

    cudaFuncSetAttribute(k_gemm1, cudaFuncAttributeMaxDynamicSharedMemorySize,
                         G1_SMEM_BYTES);

    k_zero_cnt<<<(N_NODES / 4 + 255) / 256, 256>>>();
    k_count   <<<(N_EDGES / 8 + 255) / 256, 256>>>(row);
    k_scan    <<<1, 1024>>>();
    k_place   <<<(N_EDGES / 8 + 255) / 256, 256>>>(row, col);

    k_gemm1<<<(N_NODES + G1_MT - 1) / G1_MT, G1_BLOCK, G1_SMEM_BYTES>>>(x, W1);

    k_agg1 <<<(N_NODES * 32 + 255) / 256, 256>>>(b1, W2);
    k_agg2 <<<(N_NODES * 32 + 255) / 256, 256>>>(b2, out);
}

// round 6
// speedup vs baseline: 1.1751x; 1.1751x over previous
#include <cuda_runtime.h>
#include <math.h>

#define N_NODES 100000
#define N_EDGES 3200000
#define K_IN    1433
#define C1      16

// ---------------- scratch (static device globals; no allocation) ------------
__device__ __align__(16) int   g_cnt[N_NODES];
__device__ __align__(16) int   g_off[N_NODES + 4];
__device__ __align__(16) int   g_pos[N_NODES];
__device__ __align__(16) float g_dinv[N_NODES];
__device__ __align__(16) int   g_ecol[N_EDGES];
__device__ __align__(16) float g_h1[N_NODES * 16];
__device__ __align__(16) float g_h2[N_NODES * 8];

// ---------------- degree / CSR build ---------------------------------------
__global__ void k_zero_cnt() {
    int i = blockIdx.x * blockDim.x + threadIdx.x;
    if (i * 4 < N_NODES) ((int4*)g_cnt)[i] = make_int4(0, 0, 0, 0);
}

__global__ void k_count(const int* __restrict__ row) {
    int i = blockIdx.x * blockDim.x + threadIdx.x;     // 8 edges per thread
    if (i * 8 >= N_EDGES) return;
    int4 r0 = ((const int4*)row)[2 * i];
    int4 r1 = ((const int4*)row)[2 * i + 1];
    atomicAdd(&g_cnt[r0.x], 1);
    atomicAdd(&g_cnt[r0.y], 1);
    atomicAdd(&g_cnt[r0.z], 1);
    atomicAdd(&g_cnt[r0.w], 1);
    atomicAdd(&g_cnt[r1.x], 1);
    atomicAdd(&g_cnt[r1.y], 1);
    atomicAdd(&g_cnt[r1.z], 1);
    atomicAdd(&g_cnt[r1.w], 1);
}

// single-block exclusive scan of counts -> offsets; also dinv = rsqrt(deg+1)
__global__ void k_scan() {
    const int T = 1024, ACT = 1000, CH4 = 25;          // 1000*100 = 100000
    int t = threadIdx.x;
    __shared__ int ps[T];
    int sum = 0;
    if (t < ACT) {
        const int4* c4 = (const int4*)g_cnt + t * CH4;
#pragma unroll
        for (int i = 0; i < CH4; i++) { int4 v = c4[i]; sum += v.x + v.y + v.z + v.w; }
    }
    ps[t] = sum;
    __syncthreads();
    for (int off = 1; off < T; off <<= 1) {
        int v = (t >= off) ? ps[t - off] : 0;
        __syncthreads();
        ps[t] += v;
        __syncthreads();
    }
    if (t < ACT) {
        int run = (t > 0) ? ps[t - 1] : 0;
        const int4* c4 = (const int4*)g_cnt + t * CH4;
        int4*   o4 = (int4*)g_off + t * CH4;
        int4*   p4 = (int4*)g_pos + t * CH4;
        float4* d4 = (float4*)g_dinv + t * CH4;
#pragma unroll 5
        for (int i = 0; i < CH4; i++) {
            int4 v = c4[i];
            int4 o;
            o.x = run; o.y = o.x + v.x; o.z = o.y + v.y; o.w = o.z + v.z;
            run = o.w + v.w;
            o4[i] = o; p4[i] = o;
            float4 dv;
            dv.x = rsqrtf((float)(v.x + 1)); dv.y = rsqrtf((float)(v.y + 1));
            dv.z = rsqrtf((float)(v.z + 1)); dv.w = rsqrtf((float)(v.w + 1));
            d4[i] = dv;
        }
        if (t == ACT - 1) g_off[N_NODES] = run;
    }
}

__global__ void k_place(const int* __restrict__ row, const int* __restrict__ col) {
    int i = blockIdx.x * blockDim.x + threadIdx.x;     // 8 edges per thread
    if (i * 8 >= N_EDGES) return;
    int4 r0 = ((const int4*)row)[2 * i];
    int4 r1 = ((const int4*)row)[2 * i + 1];
    int4 c0 = ((const int4*)col)[2 * i];
    int4 c1 = ((const int4*)col)[2 * i + 1];
    int p0 = atomicAdd(&g_pos[r0.x], 1);
    int p1 = atomicAdd(&g_pos[r0.y], 1);
    int p2 = atomicAdd(&g_pos[r0.z], 1);
    int p3 = atomicAdd(&g_pos[r0.w], 1);
    int p4 = atomicAdd(&g_pos[r1.x], 1);
    int p5 = atomicAdd(&g_pos[r1.y], 1);
    int p6 = atomicAdd(&g_pos[r1.z], 1);
    int p7 = atomicAdd(&g_pos[r1.w], 1);
    g_ecol[p0] = c0.x;
    g_ecol[p1] = c0.y;
    g_ecol[p2] = c0.z;
    g_ecol[p3] = c0.w;
    g_ecol[p4] = c1.x;
    g_ecol[p5] = c1.y;
    g_ecol[p6] = c1.z;
    g_ecol[p7] = c1.w;
}

// ---------------- GEMM1: h1 = x @ W1 (single-sync double buffer) -------------
#define G1_BLOCK 256
#define G1_KT    8
#define G1_MT    680
#define G1_MTP   681
#define G1_R     3
#define G1_NT    ((K_IN + G1_KT - 1) / G1_KT)
#define G1_LD    ((G1_MT * G1_KT + G1_BLOCK - 1) / G1_BLOCK)
#define WS_PAD_K 1440
#define G1_SMEM_FLOATS (WS_PAD_K * C1 + 2 * G1_KT * G1_MTP + 128)
#define G1_SMEM_BYTES  (G1_SMEM_FLOATS * 4)

__device__ __forceinline__ void ffma2(unsigned long long& d,
                                      unsigned long long a,
                                      unsigned long long b) {
    asm("fma.rn.f32x2 %0, %1, %2, %0;" : "+l"(d) : "l"(a), "l"(b));
}

__global__ void __launch_bounds__(G1_BLOCK, 1)
k_gemm1(const float* __restrict__ x, const float* __restrict__ W1) {
    extern __shared__ float sm[];
    float* ws = sm;                       // [WS_PAD_K * 16]
    float* xs = sm + WS_PAD_K * C1;       // [2][G1_KT][G1_MTP]

    const int tid = threadIdx.x;
    const int m0  = blockIdx.x * G1_MT;

    {
        const float4* W4  = (const float4*)W1;
        float4*       ws4 = (float4*)ws;
        const int nW = K_IN * C1 / 4;
        const int nP = WS_PAD_K * C1 / 4;
        for (int i = tid; i < nP; i += G1_BLOCK) {
            float4 v = make_float4(0.f, 0.f, 0.f, 0.f);
            if (i < nW) v = W4[i];
            ws4[i] = v;
        }
    }

    unsigned long long acc2[G1_R][8];
#pragma unroll
    for (int r = 0; r < G1_R; r++)
#pragma unroll
        for (int c = 0; c < 8; c++) acc2[r][c] = 0ull;

    float st[G1_LD];

#pragma unroll
    for (int u = 0; u < G1_LD; u++) {
        int i = tid + u * G1_BLOCK;
        float v = 0.f;
        if (i < G1_MT * G1_KT) {
            int k = i & (G1_KT - 1);
            int m = i >> 3;
            int gm = m0 + m, gk = k;
            if (gm < N_NODES && gk < K_IN) v = x[(size_t)gm * K_IN + gk];
        }
        st[u] = v;
    }
#pragma unroll
    for (int u = 0; u < G1_LD; u++) {
        int i = tid + u * G1_BLOCK;
        if (i < G1_MT * G1_KT) {
            int k = i & (G1_KT - 1);
            int m = i >> 3;
            xs[k * G1_MTP + m] = st[u];
        }
    }
    __syncthreads();

    for (int t = 0; t < G1_NT; t++) {
        if (t + 1 < G1_NT) {
            int k0n = (t + 1) * G1_KT;
#pragma unroll
            for (int u = 0; u < G1_LD; u++) {
                int i = tid + u * G1_BLOCK;
                float v = 0.f;
                if (i < G1_MT * G1_KT) {
                    int k = i & (G1_KT - 1);
                    int m = i >> 3;
                    int gm = m0 + m, gk = k0n + k;
                    if (gm < N_NODES && gk < K_IN) v = x[(size_t)gm * K_IN + gk];
                }
                st[u] = v;
            }
        }

        const float* xb = xs + (t & 1) * (G1_KT * G1_MTP);
        const int k0 = t * G1_KT;
#pragma unroll
        for (int k = 0; k < G1_KT; k++) {
            const ulonglong2* wrow = (const ulonglong2*)(ws + (k0 + k) * C1);
            ulonglong2 wa = wrow[0], wb = wrow[1], wc = wrow[2], wd = wrow[3];
#pragma unroll
            for (int r = 0; r < G1_R; r++) {
                float xv = xb[k * G1_MTP + (r * G1_BLOCK + tid)];
                unsigned long long xv2;
                asm("mov.b64 %0, {%1, %1};" : "=l"(xv2) : "f"(xv));
                ffma2(acc2[r][0], xv2, wa.x);
                ffma2(acc2[r][1], xv2, wa.y);
                ffma2(acc2[r][2], xv2, wb.x);
                ffma2(acc2[r][3], xv2, wb.y);
                ffma2(acc2[r][4], xv2, wc.x);
                ffma2(acc2[r][5], xv2, wc.y);
                ffma2(acc2[r][6], xv2, wd.x);
                ffma2(acc2[r][7], xv2, wd.y);
            }
        }

        // store next tile into the OTHER buffer (disjoint from the one just
        // read), then a single barrier publishes it for the next iteration.
        if (t + 1 < G1_NT) {
            float* xbn = xs + ((t + 1) & 1) * (G1_KT * G1_MTP);
#pragma unroll
            for (int u = 0; u < G1_LD; u++) {
                int i = tid + u * G1_BLOCK;
                if (i < G1_MT * G1_KT) {
                    int k = i & (G1_KT - 1);
                    int m = i >> 3;
                    xbn[k * G1_MTP + m] = st[u];
                }
            }
        }
        __syncthreads();
    }

#pragma unroll
    for (int r = 0; r < G1_R; r++) {
        int lm = r * G1_BLOCK + tid;
        int m  = m0 + lm;
        if (lm < G1_MT && m < N_NODES) {
            float4* o = (float4*)(g_h1 + (size_t)m * 16);
#pragma unroll
            for (int p = 0; p < 4; p++) {
                float2 f0, f1;
                asm("mov.b64 {%0, %1}, %2;" : "=f"(f0.x), "=f"(f0.y) : "l"(acc2[r][2 * p]));
                asm("mov.b64 {%0, %1}, %2;" : "=f"(f1.x), "=f"(f1.y) : "l"(acc2[r][2 * p + 1]));
                o[p] = make_float4(f0.x, f0.y, f1.x, f1.y);
            }
        }
    }
}

// -------- aggregation 1 + bias + relu + GEMM2 fused: ONE WARP PER NODE -------
__global__ void __launch_bounds__(256)
k_agg1(const float* __restrict__ b1, const float* __restrict__ W2) {
    __shared__ float w2s[16 * 7];
    if (threadIdx.x < 16 * 7) w2s[threadIdx.x] = W2[threadIdx.x];
    __syncthreads();

    int g = (blockIdx.x * blockDim.x + threadIdx.x) >> 5;   // node == warp
    if (g >= N_NODES) return;
    int lane = threadIdx.x & 31;
    int e = lane >> 2, q = lane & 3;

    int s = g_off[g];
    int deg = g_off[g + 1] - s;
    const int* cols = g_ecol + s;

    float4 acc = make_float4(0.f, 0.f, 0.f, 0.f);
    for (int i = e; i < deg; i += 8) {
        int c = __ldg(cols + i);
        float dw = g_dinv[c];
        float4 hv = *(const float4*)(g_h1 + (size_t)c * 16 + q * 4);
        acc.x += hv.x * dw; acc.y += hv.y * dw;
        acc.z += hv.z * dw; acc.w += hv.w * dw;
    }

#pragma unroll
    for (int o = 16; o >= 4; o >>= 1) {
        acc.x += __shfl_xor_sync(0xffffffffu, acc.x, o);
        acc.y += __shfl_xor_sync(0xffffffffu, acc.y, o);
        acc.z += __shfl_xor_sync(0xffffffffu, acc.z, o);
        acc.w += __shfl_xor_sync(0xffffffffu, acc.w, o);
    }

    float di = g_dinv[g];
    float4 self = *(const float4*)(g_h1 + (size_t)g * 16 + q * 4);
    float4 bb   = ((const float4*)b1)[q];
    float v0 = fmaxf(bb.x + di * (acc.x + di * self.x), 0.f);
    float v1 = fmaxf(bb.y + di * (acc.y + di * self.y), 0.f);
    float v2 = fmaxf(bb.z + di * (acc.z + di * self.z), 0.f);
    float v3 = fmaxf(bb.w + di * (acc.w + di * self.w), 0.f);

    float h2a[7];
    const float* w2r = w2s + (4 * q) * 7;
#pragma unroll
    for (int c2 = 0; c2 < 7; c2++)
        h2a[c2] = v0 * w2r[c2] + v1 * w2r[7 + c2] + v2 * w2r[14 + c2] + v3 * w2r[21 + c2];
#pragma unroll
    for (int o = 1; o <= 2; o <<= 1)
#pragma unroll
        for (int c2 = 0; c2 < 7; c2++)
            h2a[c2] += __shfl_xor_sync(0xffffffffu, h2a[c2], o);

    if (lane == 0) {
        float4* o4 = (float4*)(g_h2 + (size_t)g * 8);
        o4[0] = make_float4(h2a[0], h2a[1], h2a[2], h2a[3]);
        o4[1] = make_float4(h2a[4], h2a[5], h2a[6], 0.f);
    }
}

// -------- aggregation 2 + bias + log_softmax: ONE WARP PER NODE --------------
__global__ void __launch_bounds__(256)
k_agg2(const float* __restrict__ b2, float* __restrict__ out) {
    int g = (blockIdx.x * blockDim.x + threadIdx.x) >> 5;
    if (g >= N_NODES) return;
    int lane = threadIdx.x & 31;
    int e = lane >> 2, q = lane & 3;

    int s = g_off[g];
    int deg = g_off[g + 1] - s;
    const int* cols = g_ecol + s;

    float a0 = 0.f, a1 = 0.f;
    for (int i = e; i < deg; i += 8) {
        int c = __ldg(cols + i);
        float dw = g_dinv[c];
        float2 hv = *(const float2*)(g_h2 + (size_t)c * 8 + q * 2);
        a0 += hv.x * dw;
        a1 += hv.y * dw;
    }
#pragma unroll
    for (int o = 16; o >= 4; o >>= 1) {
        a0 += __shfl_xor_sync(0xffffffffu, a0, o);
        a1 += __shfl_xor_sync(0xffffffffu, a1, o);
    }

    float di = g_dinv[g];
    float dd = di * di;
    float2 self = *(const float2*)(g_h2 + (size_t)g * 8 + q * 2);
    float bb0 = b2[2 * q];
    float bb1 = (q < 3) ? b2[2 * q + 1] : 0.f;
    a0 = bb0 + di * a0 + dd * self.x;
    a1 = bb1 + di * a1 + dd * self.y;

    float m = (q == 3) ? a0 : fmaxf(a0, a1);
    m = fmaxf(m, __shfl_xor_sync(0xffffffffu, m, 1, 4));
    m = fmaxf(m, __shfl_xor_sync(0xffffffffu, m, 2, 4));
    float e0 = expf(a0 - m);
    float e1 = (q == 3) ? 0.f : expf(a1 - m);
    float ss = e0 + e1;
    ss += __shfl_xor_sync(0xffffffffu, ss, 1, 4);
    ss += __shfl_xor_sync(0xffffffffu, ss, 2, 4);
    float ls = m + logf(ss);

    if (e == 0) {
        out[(size_t)g * 7 + 2 * q] = a0 - ls;
        if (q < 3) out[(size_t)g * 7 + 2 * q + 1] = a1 - ls;
    }
}

// ---------------- launch ------------------------------------------------------
// CSR build (latency-bound) runs on a side stream concurrent with GEMM1
// (FMA-bound) via the event fork-join pattern (capture-legal).
static cudaStream_t s_csr = 0;
static cudaEvent_t  ev_fork = 0, ev_join = 0;

extern "C" void kernel_launch(void* const* d_in, const int* in_sizes, int n_in,
                              void* d_out, int out_size) {
    const float* x   = (const float*)d_in[0];
    const int*   row = (const int*)  d_in[1];
    const int*   col = (const int*)  d_in[2];
    const float* W1  = (const float*)d_in[3];
    const float* b1  = (const float*)d_in[4];
    const float* W2  = (const float*)d_in[5];
    const float* b2  = (const float*)d_in[6];
    float* out = (float*)d_out;

    if (!s_csr) {
        cudaStreamCreateWithFlags(&s_csr, cudaStreamNonBlocking);
        cudaEventCreateWithFlags(&ev_fork, cudaEventDisableTiming);
        cudaEventCreateWithFlags(&ev_join, cudaEventDisableTiming);
        cudaFuncSetAttribute(k_gemm1, cudaFuncAttributeMaxDynamicSharedMemorySize,
                             G1_SMEM_BYTES);
    }

    // fork: CSR chain onto side stream
    cudaEventRecord(ev_fork, 0);
    cudaStreamWaitEvent(s_csr, ev_fork, 0);

    k_zero_cnt<<<(N_NODES / 4 + 255) / 256, 256, 0, s_csr>>>();
    k_count   <<<(N_EDGES / 8 + 255) / 256, 256, 0, s_csr>>>(row);
    k_scan    <<<1, 1024, 0, s_csr>>>();

    // main stream: GEMM1 (submitted 4th -> lands in the profiled launch slot)
    k_gemm1<<<(N_NODES + G1_MT - 1) / G1_MT, G1_BLOCK, G1_SMEM_BYTES>>>(x, W1);

    k_place<<<(N_EDGES / 8 + 255) / 256, 256, 0, s_csr>>>(row, col);

    // join: aggregation needs both CSR and h1
    cudaEventRecord(ev_join, s_csr);
    cudaStreamWaitEvent(0, ev_join, 0);

    k_agg1<<<(N_NODES * 32 + 255) / 256, 256>>>(b1, W2);
    k_agg2<<<(N_NODES * 32 + 255) / 256, 256>>>(b2, out);
}

// round 8
// speedup vs baseline: 1.4037x; 1.1946x over previous
#include <cuda_runtime.h>
#include <math.h>

#define N_NODES 100000
#define N_EDGES 3200000
#define K_IN    1433
#define C1      16

// ---------------- scratch (static device globals; no allocation) ------------
__device__ __align__(16) int   g_cnt[N_NODES];
__device__ __align__(16) int   g_off[N_NODES + 4];
__device__ __align__(16) int   g_pos[N_NODES];
__device__ __align__(16) float g_dinv[N_NODES];
__device__ __align__(16) int   g_ecol[N_EDGES];
__device__ __align__(16) float g_h1[N_NODES * 16];
__device__ __align__(16) float g_h2[N_NODES * 8];

// ---------------- degree / CSR build ---------------------------------------
__global__ void k_zero_cnt() {
    int i = blockIdx.x * blockDim.x + threadIdx.x;
    if (i * 4 < N_NODES) ((int4*)g_cnt)[i] = make_int4(0, 0, 0, 0);
}

__global__ void k_count(const int* __restrict__ row) {
    int i = blockIdx.x * blockDim.x + threadIdx.x;     // 8 edges per thread
    if (i * 8 >= N_EDGES) return;
    int4 r0 = ((const int4*)row)[2 * i];
    int4 r1 = ((const int4*)row)[2 * i + 1];
    atomicAdd(&g_cnt[r0.x], 1);
    atomicAdd(&g_cnt[r0.y], 1);
    atomicAdd(&g_cnt[r0.z], 1);
    atomicAdd(&g_cnt[r0.w], 1);
    atomicAdd(&g_cnt[r1.x], 1);
    atomicAdd(&g_cnt[r1.y], 1);
    atomicAdd(&g_cnt[r1.z], 1);
    atomicAdd(&g_cnt[r1.w], 1);
}

// single-block exclusive scan of counts -> offsets; also dinv = rsqrt(deg+1)
__global__ void k_scan() {
    const int T = 1024, ACT = 1000, CH4 = 25;          // 1000*100 = 100000
    int t = threadIdx.x;
    __shared__ int ps[T];
    int sum = 0;
    if (t < ACT) {
        const int4* c4 = (const int4*)g_cnt + t * CH4;
#pragma unroll
        for (int i = 0; i < CH4; i++) { int4 v = c4[i]; sum += v.x + v.y + v.z + v.w; }
    }
    ps[t] = sum;
    __syncthreads();
    for (int off = 1; off < T; off <<= 1) {
        int v = (t >= off) ? ps[t - off] : 0;
        __syncthreads();
        ps[t] += v;
        __syncthreads();
    }
    if (t < ACT) {
        int run = (t > 0) ? ps[t - 1] : 0;
        const int4* c4 = (const int4*)g_cnt + t * CH4;
        int4*   o4 = (int4*)g_off + t * CH4;
        int4*   p4 = (int4*)g_pos + t * CH4;
        float4* d4 = (float4*)g_dinv + t * CH4;
#pragma unroll 5
        for (int i = 0; i < CH4; i++) {
            int4 v = c4[i];
            int4 o;
            o.x = run; o.y = o.x + v.x; o.z = o.y + v.y; o.w = o.z + v.z;
            run = o.w + v.w;
            o4[i] = o; p4[i] = o;
            float4 dv;
            dv.x = rsqrtf((float)(v.x + 1)); dv.y = rsqrtf((float)(v.y + 1));
            dv.z = rsqrtf((float)(v.z + 1)); dv.w = rsqrtf((float)(v.w + 1));
            d4[i] = dv;
        }
        if (t == ACT - 1) g_off[N_NODES] = run;
    }
}

__global__ void k_place(const int* __restrict__ row, const int* __restrict__ col) {
    int i = blockIdx.x * blockDim.x + threadIdx.x;     // 8 edges per thread
    if (i * 8 >= N_EDGES) return;
    int4 r0 = ((const int4*)row)[2 * i];
    int4 r1 = ((const int4*)row)[2 * i + 1];
    int4 c0 = ((const int4*)col)[2 * i];
    int4 c1 = ((const int4*)col)[2 * i + 1];
    int p0 = atomicAdd(&g_pos[r0.x], 1);
    int p1 = atomicAdd(&g_pos[r0.y], 1);
    int p2 = atomicAdd(&g_pos[r0.z], 1);
    int p3 = atomicAdd(&g_pos[r0.w], 1);
    int p4 = atomicAdd(&g_pos[r1.x], 1);
    int p5 = atomicAdd(&g_pos[r1.y], 1);
    int p6 = atomicAdd(&g_pos[r1.z], 1);
    int p7 = atomicAdd(&g_pos[r1.w], 1);
    g_ecol[p0] = c0.x;
    g_ecol[p1] = c0.y;
    g_ecol[p2] = c0.z;
    g_ecol[p3] = c0.w;
    g_ecol[p4] = c1.x;
    g_ecol[p5] = c1.y;
    g_ecol[p6] = c1.z;
    g_ecol[p7] = c1.w;
}

// ---------------- GEMM1: h1 = x @ W1, cp.async 4-stage pipeline --------------
#define G1_BLOCK 256
#define G1_KT    8
#define G1_MT    680
#define G1_MTP   681
#define G1_R     3
#define G1_NT    180            // ceil(1433/8); tile 179 has only k=1432 valid
#define G1_NU    22             // 680*8/256 = 21.25 -> 22 slots
#define STAGES   4
#define STAGE_FLOATS (G1_KT * G1_MTP)       // 5448
#define WS_PAD_K 1440
#define WS_FLOATS (WS_PAD_K * C1)
// +128 tail pad: compute reads masked rows up to index 5534 within the last
// stage (86 floats past STAGE_FLOATS). Reads land in the pad; values only feed
// accumulators discarded at store time. WITHOUT this pad, stage 3 reads past
// the smem allocation -> illegal address (R7 failure).
#define G1_SMEM_FLOATS (WS_FLOATS + STAGES * STAGE_FLOATS + 128)
#define G1_SMEM_BYTES  (G1_SMEM_FLOATS * 4)

__device__ __forceinline__ void ffma2(unsigned long long& d,
                                      unsigned long long a,
                                      unsigned long long b) {
    asm("fma.rn.f32x2 %0, %1, %2, %0;" : "+l"(d) : "l"(a), "l"(b));
}
__device__ __forceinline__ void cp_async4(unsigned dst, const float* src) {
    asm volatile("cp.async.ca.shared.global [%0], [%1], 4;" :: "r"(dst), "l"(src));
}
__device__ __forceinline__ void cp_commit() {
    asm volatile("cp.async.commit_group;");
}
__device__ __forceinline__ void cp_wait2() {
    asm volatile("cp.async.wait_group 2;");
}

__global__ void __launch_bounds__(G1_BLOCK, 1)
k_gemm1(const float* __restrict__ x, const float* __restrict__ W1) {
    extern __shared__ float sm[];
    float* ws = sm;                       // [1440 * 16], rows >=1433 zeroed
    float* xs = sm + WS_FLOATS;           // [STAGES][8 * 681] (+128 pad)

    const int tid = threadIdx.x;
    const int m0  = blockIdx.x * G1_MT;
    const int kk  = tid & 7;              // k within tile (u-invariant)
    const int mb  = tid >> 3;             // base m (u step = +32)

    // load W1 into smem (zero-pad rows 1433..1439)
    {
        const float4* W4  = (const float4*)W1;
        float4*       ws4 = (float4*)ws;
        const int nW = K_IN * C1 / 4;
        const int nP = WS_FLOATS / 4;
        for (int i = tid; i < nP; i += G1_BLOCK) {
            float4 v = make_float4(0.f, 0.f, 0.f, 0.f);
            if (i < nW) v = W4[i];
            ws4[i] = v;
        }
    }

    // per-thread invariants for the async copies
    bool mval[G1_NU];
#pragma unroll
    for (int u = 0; u < G1_NU; u++) {
        int m = mb + 32 * u;
        mval[u] = (m < G1_MT) && (m0 + m < N_NODES);
    }
    const float* xsrc0 = x + (size_t)(m0 + mb) * K_IN + kk;
    const unsigned xs_u32 = (unsigned)__cvta_generic_to_shared(xs);
    const unsigned dst0 = xs_u32 + (unsigned)(kk * G1_MTP + mb) * 4u;

    unsigned long long acc2[G1_R][8];
#pragma unroll
    for (int r = 0; r < G1_R; r++)
#pragma unroll
        for (int c = 0; c < 8; c++) acc2[r][c] = 0ull;

    // prologue: issue tiles 0..2
#pragma unroll
    for (int t = 0; t < 3; t++) {
        bool kv = (8 * t + kk) < K_IN;
        unsigned dst = dst0 + (unsigned)((t & (STAGES - 1)) * STAGE_FLOATS) * 4u;
        const float* src = xsrc0 + 8 * t;
#pragma unroll
        for (int u = 0; u < G1_NU; u++)
            if (mval[u] && kv) cp_async4(dst + u * 128u, src + (size_t)u * 32 * K_IN);
        cp_commit();
    }

    for (int t = 0; t < G1_NT; t++) {
        cp_wait2();
        __syncthreads();

        // issue tile t+3 into stage (t-1)&3 (free: all warps finished t-1)
        if (t + 3 < G1_NT) {
            int tn = t + 3;
            bool kv = (8 * tn + kk) < K_IN;
            unsigned dst = dst0 + (unsigned)((tn & (STAGES - 1)) * STAGE_FLOATS) * 4u;
            const float* src = xsrc0 + 8 * tn;
#pragma unroll
            for (int u = 0; u < G1_NU; u++)
                if (mval[u] && kv) cp_async4(dst + u * 128u, src + (size_t)u * 32 * K_IN);
        }
        cp_commit();

        const float* xb = xs + (t & (STAGES - 1)) * STAGE_FLOATS;
#pragma unroll
        for (int k = 0; k < G1_KT; k++) {
            const ulonglong2* wrow = (const ulonglong2*)(ws + (t * G1_KT + k) * C1);
            ulonglong2 wa = wrow[0], wb = wrow[1], wc = wrow[2], wd = wrow[3];
#pragma unroll
            for (int r = 0; r < G1_R; r++) {
                float xv = xb[k * G1_MTP + (r * G1_BLOCK + tid)];
                unsigned long long xv2;
                asm("mov.b64 %0, {%1, %1};" : "=l"(xv2) : "f"(xv));
                ffma2(acc2[r][0], xv2, wa.x);
                ffma2(acc2[r][1], xv2, wa.y);
                ffma2(acc2[r][2], xv2, wb.x);
                ffma2(acc2[r][3], xv2, wb.y);
                ffma2(acc2[r][4], xv2, wc.x);
                ffma2(acc2[r][5], xv2, wc.y);
                ffma2(acc2[r][6], xv2, wd.x);
                ffma2(acc2[r][7], xv2, wd.y);
            }
        }
    }

#pragma unroll
    for (int r = 0; r < G1_R; r++) {
        int lm = r * G1_BLOCK + tid;
        int m  = m0 + lm;
        if (lm < G1_MT && m < N_NODES) {
            float4* o = (float4*)(g_h1 + (size_t)m * 16);
#pragma unroll
            for (int p = 0; p < 4; p++) {
                float2 f0, f1;
                asm("mov.b64 {%0, %1}, %2;" : "=f"(f0.x), "=f"(f0.y) : "l"(acc2[r][2 * p]));
                asm("mov.b64 {%0, %1}, %2;" : "=f"(f1.x), "=f"(f1.y) : "l"(acc2[r][2 * p + 1]));
                o[p] = make_float4(f0.x, f0.y, f1.x, f1.y);
            }
        }
    }
}

// -------- aggregation 1 + bias + relu + GEMM2 fused: ONE WARP PER NODE -------
__global__ void __launch_bounds__(256)
k_agg1(const float* __restrict__ b1, const float* __restrict__ W2) {
    __shared__ float w2s[16 * 7];
    if (threadIdx.x < 16 * 7) w2s[threadIdx.x] = W2[threadIdx.x];
    __syncthreads();

    int g = (blockIdx.x * blockDim.x + threadIdx.x) >> 5;   // node == warp
    if (g >= N_NODES) return;
    int lane = threadIdx.x & 31;
    int e = lane >> 2, q = lane & 3;

    int s = g_off[g];
    int deg = g_off[g + 1] - s;
    const int* cols = g_ecol + s;

    float4 acc = make_float4(0.f, 0.f, 0.f, 0.f);
    for (int i = e; i < deg; i += 8) {
        int c = __ldg(cols + i);
        float dw = g_dinv[c];
        float4 hv = *(const float4*)(g_h1 + (size_t)c * 16 + q * 4);
        acc.x += hv.x * dw; acc.y += hv.y * dw;
        acc.z += hv.z * dw; acc.w += hv.w * dw;
    }

#pragma unroll
    for (int o = 16; o >= 4; o >>= 1) {
        acc.x += __shfl_xor_sync(0xffffffffu, acc.x, o);
        acc.y += __shfl_xor_sync(0xffffffffu, acc.y, o);
        acc.z += __shfl_xor_sync(0xffffffffu, acc.z, o);
        acc.w += __shfl_xor_sync(0xffffffffu, acc.w, o);
    }

    float di = g_dinv[g];
    float4 self = *(const float4*)(g_h1 + (size_t)g * 16 + q * 4);
    float4 bb   = ((const float4*)b1)[q];
    float v0 = fmaxf(bb.x + di * (acc.x + di * self.x), 0.f);
    float v1 = fmaxf(bb.y + di * (acc.y + di * self.y), 0.f);
    float v2 = fmaxf(bb.z + di * (acc.z + di * self.z), 0.f);
    float v3 = fmaxf(bb.w + di * (acc.w + di * self.w), 0.f);

    float h2a[7];
    const float* w2r = w2s + (4 * q) * 7;
#pragma unroll
    for (int c2 = 0; c2 < 7; c2++)
        h2a[c2] = v0 * w2r[c2] + v1 * w2r[7 + c2] + v2 * w2r[14 + c2] + v3 * w2r[21 + c2];
#pragma unroll
    for (int o = 1; o <= 2; o <<= 1)
#pragma unroll
        for (int c2 = 0; c2 < 7; c2++)
            h2a[c2] += __shfl_xor_sync(0xffffffffu, h2a[c2], o);

    if (lane == 0) {
        float4* o4 = (float4*)(g_h2 + (size_t)g * 8);
        o4[0] = make_float4(h2a[0], h2a[1], h2a[2], h2a[3]);
        o4[1] = make_float4(h2a[4], h2a[5], h2a[6], 0.f);
    }
}

// -------- aggregation 2 + bias + log_softmax: ONE WARP PER NODE --------------
__global__ void __launch_bounds__(256)
k_agg2(const float* __restrict__ b2, float* __restrict__ out) {
    int g = (blockIdx.x * blockDim.x + threadIdx.x) >> 5;
    if (g >= N_NODES) return;
    int lane = threadIdx.x & 31;
    int e = lane >> 2, q = lane & 3;

    int s = g_off[g];
    int deg = g_off[g + 1] - s;
    const int* cols = g_ecol + s;

    float a0 = 0.f, a1 = 0.f;
    for (int i = e; i < deg; i += 8) {
        int c = __ldg(cols + i);
        float dw = g_dinv[c];
        float2 hv = *(const float2*)(g_h2 + (size_t)c * 8 + q * 2);
        a0 += hv.x * dw;
        a1 += hv.y * dw;
    }
#pragma unroll
    for (int o = 16; o >= 4; o >>= 1) {
        a0 += __shfl_xor_sync(0xffffffffu, a0, o);
        a1 += __shfl_xor_sync(0xffffffffu, a1, o);
    }

    float di = g_dinv[g];
    float dd = di * di;
    float2 self = *(const float2*)(g_h2 + (size_t)g * 8 + q * 2);
    float bb0 = b2[2 * q];
    float bb1 = (q < 3) ? b2[2 * q + 1] : 0.f;
    a0 = bb0 + di * a0 + dd * self.x;
    a1 = bb1 + di * a1 + dd * self.y;

    float m = (q == 3) ? a0 : fmaxf(a0, a1);
    m = fmaxf(m, __shfl_xor_sync(0xffffffffu, m, 1, 4));
    m = fmaxf(m, __shfl_xor_sync(0xffffffffu, m, 2, 4));
    float e0 = expf(a0 - m);
    float e1 = (q == 3) ? 0.f : expf(a1 - m);
    float ss = e0 + e1;
    ss += __shfl_xor_sync(0xffffffffu, ss, 1, 4);
    ss += __shfl_xor_sync(0xffffffffu, ss, 2, 4);
    float ls = m + logf(ss);

    if (e == 0) {
        out[(size_t)g * 7 + 2 * q] = a0 - ls;
        if (q < 3) out[(size_t)g * 7 + 2 * q + 1] = a1 - ls;
    }
}

// ---------------- launch ------------------------------------------------------
static cudaStream_t s_csr = 0;
static cudaEvent_t  ev_fork = 0, ev_join = 0;

extern "C" void kernel_launch(void* const* d_in, const int* in_sizes, int n_in,
                              void* d_out, int out_size) {
    const float* x   = (const float*)d_in[0];
    const int*   row = (const int*)  d_in[1];
    const int*   col = (const int*)  d_in[2];
    const float* W1  = (const float*)d_in[3];
    const float* b1  = (const float*)d_in[4];
    const float* W2  = (const float*)d_in[5];
    const float* b2  = (const float*)d_in[6];
    float* out = (float*)d_out;

    if (!s_csr) {
        cudaStreamCreateWithFlags(&s_csr, cudaStreamNonBlocking);
        cudaEventCreateWithFlags(&ev_fork, cudaEventDisableTiming);
        cudaEventCreateWithFlags(&ev_join, cudaEventDisableTiming);
        cudaFuncSetAttribute(k_gemm1, cudaFuncAttributeMaxDynamicSharedMemorySize,
                             G1_SMEM_BYTES);
    }

    // fork: CSR chain onto side stream (overlaps with GEMM1)
    cudaEventRecord(ev_fork, 0);
    cudaStreamWaitEvent(s_csr, ev_fork, 0);

    k_zero_cnt<<<(N_NODES / 4 + 255) / 256, 256, 0, s_csr>>>();
    k_count   <<<(N_EDGES / 8 + 255) / 256, 256, 0, s_csr>>>(row);
    k_scan    <<<1, 1024, 0, s_csr>>>();

    // main stream: GEMM1
    k_gemm1<<<(N_NODES + G1_MT - 1) / G1_MT, G1_BLOCK, G1_SMEM_BYTES>>>(x, W1);

    k_place<<<(N_EDGES / 8 + 255) / 256, 256, 0, s_csr>>>(row, col);

    // join: aggregation needs both CSR and h1
    cudaEventRecord(ev_join, s_csr);
    cudaStreamWaitEvent(0, ev_join, 0);

    k_agg1<<<(N_NODES * 32 + 255) / 256, 256>>>(b1, W2);
    k_agg2<<<(N_NODES * 32 + 255) / 256, 256>>>(b2, out);
}